// round 10
// baseline (speedup 1.0000x reference)
#include <cuda_runtime.h>
#include <cuda_fp16.h>
#include <cstdint>

#define N_HEADS 4
#define H_DIM   128
#define TOK_F   512
#define K_DIM   4096
#define BLK     32
#define STRIDE  16
#define MAXSEQ  256

#define NSTEPS  64
#define KT      64              // K halves per step
#define A_BYTES 8192            // 64 rows x 128B
#define B_BYTES 16384           // 128 rows x 128B
#define SMEM_GEMM (2 * A_BYTES + 4 * B_BYTES + 128)

// ---------------- device scratch ----------------
__device__ int    g_bases[65536];
__device__ int    g_total_out;
__device__ __half g_wT[2][(size_t)K_DIM * H_DIM];   // [mat][n*4096 + k] = w[k*128+n]

static __device__ __forceinline__ uint32_t smem_u32(const void* p) {
    uint32_t a;
    asm("{ .reg .u64 t; cvta.to.shared.u64 t, %1; cvt.u32.u64 %0, t; }" : "=r"(a) : "l"(p));
    return a;
}

#define CP_ASYNC16(dst, src) \
    asm volatile("cp.async.cg.shared.global [%0], [%1], 16;" :: "r"(dst), "l"(src) : "memory")
#define CP_COMMIT()  asm volatile("cp.async.commit_group;" ::: "memory")
#define CP_WAITALL() asm volatile("cp.async.wait_all;" ::: "memory")

#define BAR_HALF(id) \
    asm volatile("bar.sync %0, 256;" :: "r"(id) : "memory")

#define LDMATRIX_X4(r0, r1, r2, r3, addr) \
    asm volatile("ldmatrix.sync.aligned.m8n8.x4.shared.b16 {%0,%1,%2,%3}, [%4];" \
                 : "=r"(r0), "=r"(r1), "=r"(r2), "=r"(r3) : "r"(addr))

// fp16-accumulate MMA: D,C packed half2 x2
#define MMAF16(c, a0, a1, a2, a3, b0, b1) \
    asm volatile("mma.sync.aligned.m16n8k16.row.col.f16.f16.f16.f16 " \
                 "{%0,%1}, {%2,%3,%4,%5}, {%6,%7}, {%0,%1};" \
                 : "+r"((c)[0]), "+r"((c)[1]) \
                 : "r"(a0), "r"(a1), "r"(a2), "r"(a3), "r"(b0), "r"(b1))

// ---------------- kernel 1: prep = ragged metadata + W transpose/convert ----------------
__global__ void prep_kernel(const int* __restrict__ cu, int nseq,
                            const float* __restrict__ wk, const float* __restrict__ wv,
                            float* __restrict__ dout) {
    if (blockIdx.x == 1024) {
        __shared__ int s_ol[MAXSEQ];
        __shared__ int s_cu[MAXSEQ + 1];
        int t = threadIdx.y * 32 + threadIdx.x;
        if (t < nseq) {
            int n = cu[t + 1] - cu[t];
            s_ol[t] = (n >= BLK) ? (n - BLK) / STRIDE : 0;
        }
        __syncthreads();
        if (t == 0) {
            int acc = 0;
            s_cu[0] = 0;
            for (int b = 0; b < nseq; b++) { acc += s_ol[b]; s_cu[b + 1] = acc; }
            g_total_out = acc;
        }
        __syncthreads();
        int total = s_cu[nseq];
        for (int i = t; i <= nseq; i += 256)
            dout[(size_t)2 * total * 512 + i] = (float)s_cu[i];
        for (int o = t; o < total; o += 256) {
            int b = 0;
            while (s_cu[b + 1] <= o) b++;
            g_bases[o] = cu[b] + (o - s_cu[b]) * STRIDE;
        }
        return;
    }
    __shared__ float tile[32][33];
    int bx = blockIdx.x;
    int z   = bx >> 9;
    int rem = bx & 511;
    int kb  = rem & 127;
    int nb  = rem >> 7;
    const float* w = z ? wv : wk;
    __half* out = g_wT[z];
    int k0 = kb * 32, n0 = nb * 32;
    int tx = threadIdx.x, ty = threadIdx.y;   // (32, 8)
#pragma unroll
    for (int i = 0; i < 32; i += 8)
        tile[ty + i][tx] = w[(size_t)(k0 + ty + i) * H_DIM + n0 + tx];
    __syncthreads();
#pragma unroll
    for (int i = 0; i < 32; i += 8)
        out[(size_t)(n0 + ty + i) * K_DIM + k0 + tx] = __float2half_rn(tile[tx][ty + i]);
}

// convert 2 float4 (8 fp32) -> 1 swizzled uint4 (8 fp16) store
static __device__ __forceinline__ void cvt_store_A8(char* smem, uint32_t ast,
                                                    float4 v0, float4 v1) {
    __half2 h;
    uint4 st;
    h = __floats2half2_rn(v0.x, v0.y); st.x = *(uint32_t*)&h;
    h = __floats2half2_rn(v0.z, v0.w); st.y = *(uint32_t*)&h;
    h = __floats2half2_rn(v1.x, v1.y); st.z = *(uint32_t*)&h;
    h = __floats2half2_rn(v1.z, v1.w); st.w = *(uint32_t*)&h;
    *(uint4*)(smem + ast) = st;
}

// ---------------- kernel 2: HMMA GEMM ----------------
// 512 thr = 16 warps in 2(M) x 8(N); warp tile 32x16; CTA tile 64x128; K-step 64.
// 2 CTAs/SM -> 32 warps/SM (forced <=64 regs). R9's sync scheme: one full
// __syncthreads per 2 steps (B quad-buffer + wait_all), A via half barriers.
__global__ __launch_bounds__(512, 2)
void gemm_kernel(const float* __restrict__ kin, const float* __restrict__ vin,
                 float* __restrict__ dout) {
    extern __shared__ __align__(128) char smem[];
    const uint32_t sa = smem_u32(smem);            // A: 2 x 8KB
    const uint32_t sb = sa + 2 * A_BYTES;          // B: 4 x 16KB
    int* s_base = (int*)(smem + 2 * A_BYTES + 4 * B_BYTES);

    const int tid = threadIdx.x;
    const int wid = tid >> 5;
    const int lid = tid & 31;
    const int total_out = g_total_out;
    const int o0 = blockIdx.x * 16;               // 16 output blocks (64 rows) per CTA
    if (o0 >= total_out) return;

    const int mat = blockIdx.y;
    const float* __restrict__ x = mat ? vin : kin;
    const __half* __restrict__ wT = g_wT[mat];
    float* __restrict__ outp = dout + (size_t)mat * (size_t)total_out * 512;

    if (tid < 16) {
        int o = o0 + tid;
        if (o >= total_out) o = total_out - 1;
        s_base[tid] = g_bases[o];
    }
    __syncthreads();

    // ---- A writer: half h = tid>>8 owns rows h*32..+31 (matches reader half wm) ----
    const int ht    = tid & 255;
    const int m_row = (tid >> 8) * 32 + (ht >> 3);
    const int q     = tid & 7;                    // 8 floats per thread per row-chunk
    const float* aptr = x + (size_t)s_base[m_row >> 2] * TOK_F
                          + (size_t)(m_row & 3) * H_DIM + q * 8;
    const uint32_t ast = (uint32_t)(m_row * 128 + ((q ^ (m_row & 7)) * 16));

    // ---- B cp.async: thread handles n = tid>>2, chunks (tid&3)*2 + {0,1} ----
    const __half* bsrc0;
    uint32_t bdst0, bdst1;
    {
        int n = tid >> 2, c0 = (tid & 3) * 2;
        bsrc0 = wT + (size_t)n * K_DIM + c0 * 8;
        bdst0 = sb + (uint32_t)(n * 128 + ((c0 ^ (n & 7)) * 16));
        bdst1 = sb + (uint32_t)(n * 128 + (((c0 + 1) ^ (n & 7)) * 16));
    }

    // ---- ldmatrix addresses ----
    const int wm = wid >> 3;       // M position 0..1 (32 rows each)
    const int nc = wid & 7;        // N position 0..7 (16 cols each)
    const int g  = lid >> 3;       // tile group 0..3
    const int l7 = lid & 7;
    // A: ma in {0,1}: row = wm*32 + ma*16 + (g&1)*8 + l7, chunk = 2*k16i + (g>>1)
    uint32_t lma[2][4];
#pragma unroll
    for (int ma = 0; ma < 2; ma++) {
        int r = wm * 32 + ma * 16 + (g & 1) * 8 + l7;
#pragma unroll
        for (int k16i = 0; k16i < 4; k16i++) {
            int c = (2 * k16i + (g >> 1)) ^ (r & 7);
            lma[ma][k16i] = sa + (uint32_t)(r * 128 + c * 16);
        }
    }
    // B: single x4 per k16i covering both n-atoms: n = nc*16 + (g>>1)*8 + l7,
    //    chunk = 2*k16i + (g&1)
    uint32_t lmb[4];
    {
        int n = nc * 16 + (g >> 1) * 8 + l7;
#pragma unroll
        for (int k16i = 0; k16i < 4; k16i++) {
            int c = (2 * k16i + (g & 1)) ^ (n & 7);
            lmb[k16i] = sb + (uint32_t)(n * 128 + c * 16);
        }
    }

    float acc[4][4];             // fp32 masters [tile = ma*2+na][e]
    uint32_t facc[4][2];         // fp16 window accumulators
#pragma unroll
    for (int t = 0; t < 4; t++) {
#pragma unroll
        for (int e = 0; e < 4; e++) acc[t][e] = 0.f;
        facc[t][0] = 0u; facc[t][1] = 0u;
    }

    // ---- prologue: B steps 0,1; A step 0 -> slot 0 ----
    CP_ASYNC16(bdst0, bsrc0);
    CP_ASYNC16(bdst1, bsrc0 + 8);
    CP_COMMIT();
    CP_ASYNC16(bdst0 + B_BYTES, bsrc0 + KT);
    CP_ASYNC16(bdst1 + B_BYTES, bsrc0 + KT + 8);
    CP_COMMIT();
    {
        float4 v0 = *(const float4*)(aptr);
        float4 v1 = *(const float4*)(aptr + 4);
        cvt_store_A8(smem, ast, v0, v1);
    }

#pragma unroll 1
    for (int s = 0; s < NSTEPS; s += 2) {
        CP_WAITALL();
        __syncthreads();

        // issue B for steps s+2, s+3 (slots (s+2)&3, (s+3)&3)
        if (s + 2 < NSTEPS) {
            const int koff = (s + 2) * KT;
            CP_ASYNC16(bdst0 + ((s + 2) & 3) * B_BYTES, bsrc0 + koff);
            CP_ASYNC16(bdst1 + ((s + 2) & 3) * B_BYTES, bsrc0 + koff + 8);
            CP_COMMIT();
        }
        if (s + 3 < NSTEPS) {
            const int koff = (s + 3) * KT;
            CP_ASYNC16(bdst0 + ((s + 3) & 3) * B_BYTES, bsrc0 + koff);
            CP_ASYNC16(bdst1 + ((s + 3) & 3) * B_BYTES, bsrc0 + koff + 8);
            CP_COMMIT();
        }

        // ======== step s (even): A slot 0, B slot s&3 ========
        float4 v0, v1;
        {   // prefetch A(s+1)
            const int aoff = ((s + 1) >> 1) * TOK_F + ((s + 1) & 1) * KT;
            v0 = *(const float4*)(aptr + aoff);
            v1 = *(const float4*)(aptr + aoff + 4);
        }
        {
            const uint32_t bbuf = (uint32_t)((s & 3) * B_BYTES);
#pragma unroll
            for (int k16i = 0; k16i < 4; k16i++) {
                uint32_t a0[4], a1[4], b[4];
                LDMATRIX_X4(a0[0], a0[1], a0[2], a0[3], lma[0][k16i]);
                LDMATRIX_X4(a1[0], a1[1], a1[2], a1[3], lma[1][k16i]);
                LDMATRIX_X4(b[0], b[1], b[2], b[3], lmb[k16i] + bbuf);
                MMAF16(facc[0], a0[0], a0[1], a0[2], a0[3], b[0], b[1]);
                MMAF16(facc[1], a0[0], a0[1], a0[2], a0[3], b[2], b[3]);
                MMAF16(facc[2], a1[0], a1[1], a1[2], a1[3], b[0], b[1]);
                MMAF16(facc[3], a1[0], a1[1], a1[2], a1[3], b[2], b[3]);
            }
        }
        // store A(s+1) -> slot 1
        cvt_store_A8(smem + A_BYTES, ast, v0, v1);
        BAR_HALF(1 + wm);   // publish A slot 1 within this half

        // ======== step s+1 (odd): A slot 1, B slot (s+1)&3 ========
        const bool pf2 = (s + 2 < NSTEPS);
        if (pf2) {
            const int aoff = ((s + 2) >> 1) * TOK_F + ((s + 2) & 1) * KT;
            v0 = *(const float4*)(aptr + aoff);
            v1 = *(const float4*)(aptr + aoff + 4);
        }
        {
            const uint32_t bbuf = (uint32_t)(((s + 1) & 3) * B_BYTES);
#pragma unroll
            for (int k16i = 0; k16i < 4; k16i++) {
                uint32_t a0[4], a1[4], b[4];
                LDMATRIX_X4(a0[0], a0[1], a0[2], a0[3], lma[0][k16i] + A_BYTES);
                LDMATRIX_X4(a1[0], a1[1], a1[2], a1[3], lma[1][k16i] + A_BYTES);
                LDMATRIX_X4(b[0], b[1], b[2], b[3], lmb[k16i] + bbuf);
                MMAF16(facc[0], a0[0], a0[1], a0[2], a0[3], b[0], b[1]);
                MMAF16(facc[1], a0[0], a0[1], a0[2], a0[3], b[2], b[3]);
                MMAF16(facc[2], a1[0], a1[1], a1[2], a1[3], b[0], b[1]);
                MMAF16(facc[3], a1[0], a1[1], a1[2], a1[3], b[2], b[3]);
            }
        }
        // flush fp16 window into fp32 (window = steps s, s+1)
#pragma unroll
        for (int t = 0; t < 4; t++) {
            float2 f0 = __half22float2(*reinterpret_cast<__half2*>(&facc[t][0]));
            float2 f1 = __half22float2(*reinterpret_cast<__half2*>(&facc[t][1]));
            acc[t][0] += f0.x; acc[t][1] += f0.y;
            acc[t][2] += f1.x; acc[t][3] += f1.y;
            facc[t][0] = 0u; facc[t][1] = 0u;
        }
        // store A(s+2) -> slot 0
        if (pf2) cvt_store_A8(smem, ast, v0, v1);
    }

    // ---- epilogue ----
    const int Rmax = total_out * 4;
    const int l4 = lid >> 2, lc = lid & 3;
#pragma unroll
    for (int ma = 0; ma < 2; ma++) {
        int R0 = o0 * 4 + wm * 32 + ma * 16 + l4;
#pragma unroll
        for (int na = 0; na < 2; na++) {
            int col = nc * 16 + na * 8 + lc * 2;
            const float* a = acc[ma * 2 + na];
            if (R0 < Rmax)
                *(float2*)(outp + (size_t)R0 * 128 + col) = make_float2(a[0], a[1]);
            if (R0 + 8 < Rmax)
                *(float2*)(outp + (size_t)(R0 + 8) * 128 + col) = make_float2(a[2], a[3]);
        }
    }
}

// ---------------- launch ----------------
extern "C" void kernel_launch(void* const* d_in, const int* in_sizes, int n_in,
                              void* d_out, int out_size) {
    const float* k  = (const float*)d_in[0];
    const float* v  = (const float*)d_in[1];
    const float* wk = (const float*)d_in[2];
    const float* wv = (const float*)d_in[3];
    const int*   cu = (const int*)d_in[4];
    int nseq = in_sizes[4] - 1;
    int total_tokens = in_sizes[0] / (N_HEADS * H_DIM);

    prep_kernel<<<1025, dim3(32, 8)>>>(cu, nseq, wk, wv, (float*)d_out);

    int max_out = total_tokens / STRIDE;
    int ntiles = (max_out + 15) / 16;
    cudaFuncSetAttribute(gemm_kernel, cudaFuncAttributeMaxDynamicSharedMemorySize, SMEM_GEMM);
    gemm_kernel<<<dim3(ntiles, 2), 512, SMEM_GEMM>>>(k, v, (float*)d_out);
}